// round 1
// baseline (speedup 1.0000x reference)
#include <cuda_runtime.h>

// BillehColumn GLIF3 simulation, forward only.
// Structure per launch (all graph-capturable, no allocations):
//   1. init state + zero counts
//   2. histogram of pre_idx -> counts
//   3. 3-kernel exclusive scan -> row offsets (CSR by pre neuron)
//   4. fill CSR (target slot = post*4+receptor, weight)
//   5. 50x step kernel: neuron update fused with push-scatter of spikes
//      into the NEXT step's rec_in buffer (double buffered).

#define Nn 100000
#define Rr 4
#define Ee 2000000
#define Tt 50
#define NRr (Nn * Rr)
#define SCAN_BLOCKS 98   // ceil(100000/1024)

__device__ float g_v[Nn];
__device__ float g_r[Nn];
__device__ float g_z[Nn];
__device__ float g_asc[Nn * 2];
__device__ float g_psc[NRr];
__device__ float g_psc_rise[NRr];
__device__ float g_rec[2][NRr];
__device__ int   g_cnt[Nn];
__device__ int   g_offs[Nn];
__device__ int   g_cursor[Nn];
__device__ int   g_syn_tgt[Ee];
__device__ float g_syn_w[Ee];
__device__ int   g_bsum[128];

// ---------------------------------------------------------------------------
// Init: zero all state, copy v0, zero counts and both rec buffers.
// Grid covers NR (largest range); smaller ranges guarded.
__global__ void k_init(const float* __restrict__ v0) {
    int i = blockIdx.x * blockDim.x + threadIdx.x;
    if (i < NRr) {
        g_psc[i] = 0.f;
        g_psc_rise[i] = 0.f;
        g_rec[0][i] = 0.f;
        g_rec[1][i] = 0.f;
    }
    if (i < Nn * 2) {
        g_asc[i] = 0.f;
    }
    if (i < Nn) {
        g_v[i] = v0[i];
        g_r[i] = 0.f;
        g_z[i] = 0.f;
        g_cnt[i] = 0;
    }
}

// Histogram of synapse pre-neuron ids.
__global__ void k_hist(const int* __restrict__ pre) {
    int e = blockIdx.x * blockDim.x + threadIdx.x;
    if (e < Ee) atomicAdd(&g_cnt[pre[e]], 1);
}

// Block-level exclusive scan of g_cnt -> g_offs, block sums -> g_bsum.
__global__ void k_scan1() {
    __shared__ int sh[1024];
    int tid = threadIdx.x;
    int idx = blockIdx.x * 1024 + tid;
    int v = (idx < Nn) ? g_cnt[idx] : 0;
    sh[tid] = v;
    __syncthreads();
#pragma unroll
    for (int off = 1; off < 1024; off <<= 1) {
        int t = (tid >= off) ? sh[tid - off] : 0;
        __syncthreads();
        sh[tid] += t;
        __syncthreads();
    }
    int inc = sh[tid];
    if (idx < Nn) g_offs[idx] = inc - v;
    if (tid == 1023) g_bsum[blockIdx.x] = inc;
}

// Exclusive scan of block sums (SCAN_BLOCKS <= 128), single block of 128.
__global__ void k_scan2() {
    __shared__ int sh[128];
    int tid = threadIdx.x;
    int v = (tid < SCAN_BLOCKS) ? g_bsum[tid] : 0;
    sh[tid] = v;
    __syncthreads();
#pragma unroll
    for (int off = 1; off < 128; off <<= 1) {
        int t = (tid >= off) ? sh[tid - off] : 0;
        __syncthreads();
        sh[tid] += t;
        __syncthreads();
    }
    g_bsum[tid] = sh[tid] - v;  // exclusive
}

// Add block bases; init scatter cursors.
__global__ void k_scan3() {
    int i = blockIdx.x * blockDim.x + threadIdx.x;
    if (i < Nn) {
        int o = g_offs[i] + g_bsum[i >> 10];
        g_offs[i] = o;
        g_cursor[i] = o;
    }
}

// Fill CSR: synapses grouped by pre neuron.
__global__ void k_fill(const int* __restrict__ pre,
                       const int* __restrict__ post,
                       const int* __restrict__ rcp,
                       const float* __restrict__ w) {
    int e = blockIdx.x * blockDim.x + threadIdx.x;
    if (e < Ee) {
        int p = pre[e];
        int pos = atomicAdd(&g_cursor[p], 1);
        g_syn_tgt[pos] = post[e] * Rr + rcp[e];
        g_syn_w[pos] = w[e];
    }
}

// ---------------------------------------------------------------------------
// One timestep: reads rec[parity] (scattered by previous step's spikes),
// zeroes it for reuse, runs GLIF3 dynamics, writes spikes to out, and
// push-scatters this step's spikes into rec[parity^1] for the next step.
__global__ void k_step(const float* __restrict__ x_t,
                       float* __restrict__ out,
                       const float* __restrict__ vth,
                       const float* __restrict__ vreset,
                       const float* __restrict__ tref,
                       const float* __restrict__ decay,
                       const float* __restrict__ cf,
                       const float* __restrict__ el,
                       const float* __restrict__ amps,
                       const float* __restrict__ ascd,
                       const float* __restrict__ syn_decay,
                       const float* __restrict__ psc_init,
                       int parity) {
    int n = blockIdx.x * blockDim.x + threadIdx.x;
    if (n >= Nn) return;

    const float4 sd = *(const float4*)syn_decay;
    const float4 pi = *(const float4*)psc_init;

    float* rec_cur = g_rec[parity];
    float* rec_nxt = g_rec[parity ^ 1];

    float4 rec = *(float4*)(&rec_cur[4 * n]);
    *(float4*)(&rec_cur[4 * n]) = make_float4(0.f, 0.f, 0.f, 0.f);

    float4 x   = ((const float4*)x_t)[n];
    float4 psc = *(float4*)(&g_psc[4 * n]);
    float4 pr  = *(float4*)(&g_psc_rise[4 * n]);

    // inputs = rec_in + x_t
    float in0 = rec.x + x.x;
    float in1 = rec.y + x.y;
    float in2 = rec.z + x.z;
    float in3 = rec.w + x.w;

    // new_psc_rise = psc_rise*sd + inputs*pi ; new_psc = psc*sd + sd*psc_rise (DT=1)
    float4 npr, npsc;
    npr.x = pr.x * sd.x + in0 * pi.x;
    npr.y = pr.y * sd.y + in1 * pi.y;
    npr.z = pr.z * sd.z + in2 * pi.z;
    npr.w = pr.w * sd.w + in3 * pi.w;
    npsc.x = psc.x * sd.x + sd.x * pr.x;
    npsc.y = psc.y * sd.y + sd.y * pr.y;
    npsc.z = psc.z * sd.z + sd.z * pr.z;
    npsc.w = psc.w * sd.w + sd.w * pr.w;

    *(float4*)(&g_psc[4 * n]) = npsc;
    *(float4*)(&g_psc_rise[4 * n]) = npr;

    float psum = ((npsc.x + npsc.y) + npsc.z) + npsc.w;

    float z = g_z[n];
    float2 a   = *(float2*)(&g_asc[2 * n]);
    float2 am  = *(const float2*)(&amps[2 * n]);
    float2 ad  = *(const float2*)(&ascd[2 * n]);

    float input_current = psum + (a.x + a.y);   // uses OLD asc

    float2 na;
    na.x = ad.x * a.x + z * am.x;
    na.y = ad.y * a.y + z * am.y;
    *(float2*)(&g_asc[2 * n]) = na;

    float vthn = vth[n];
    float nv = decay[n] * g_v[n] + cf[n] * (input_current + el[n])
             + z * (vreset[n] - vthn);
    float vsc = (nv - vthn) / vthn;

    float rold = g_r[n];
    float zn = (vsc > 0.f) ? 1.f : 0.f;
    if (rold > 0.f) zn = 0.f;
    float rn = fmaxf(rold - 1.f + zn * tref[n], 0.f);

    g_v[n] = nv;
    g_r[n] = rn;
    g_z[n] = zn;
    out[n] = zn;

    // Push-scatter this neuron's spike into the next step's rec buffer.
    if (zn != 0.f) {
        int s = g_offs[n];
        int e = s + g_cnt[n];
        for (; s < e; s++) {
            atomicAdd(&rec_nxt[g_syn_tgt[s]], g_syn_w[s]);
        }
    }
}

// ---------------------------------------------------------------------------
extern "C" void kernel_launch(void* const* d_in, const int* in_sizes, int n_in,
                              void* d_out, int out_size) {
    const float* w_rec     = (const float*)d_in[0];
    const float* x_ext     = (const float*)d_in[1];
    const float* v0        = (const float*)d_in[2];
    const float* vth       = (const float*)d_in[3];
    const float* vreset    = (const float*)d_in[4];
    const float* tref      = (const float*)d_in[5];
    const float* decay     = (const float*)d_in[6];
    const float* cf        = (const float*)d_in[7];
    const float* el        = (const float*)d_in[8];
    const float* amps      = (const float*)d_in[9];
    const float* ascd      = (const float*)d_in[10];
    const float* syn_decay = (const float*)d_in[11];
    const float* psc_init  = (const float*)d_in[12];
    const int*   pre       = (const int*)d_in[13];
    const int*   post      = (const int*)d_in[14];
    const int*   rcp       = (const int*)d_in[15];
    float* out = (float*)d_out;

    k_init<<<(NRr + 255) / 256, 256>>>(v0);
    k_hist<<<(Ee + 255) / 256, 256>>>(pre);
    k_scan1<<<SCAN_BLOCKS, 1024>>>();
    k_scan2<<<1, 128>>>();
    k_scan3<<<(Nn + 255) / 256, 256>>>();
    k_fill<<<(Ee + 255) / 256, 256>>>(pre, post, rcp, w_rec);

    for (int t = 0; t < Tt; t++) {
        k_step<<<(Nn + 255) / 256, 256>>>(
            x_ext + (size_t)t * NRr,
            out + (size_t)t * Nn,
            vth, vreset, tref, decay, cf, el, amps, ascd,
            syn_decay, psc_init, t & 1);
    }
}